// round 11
// baseline (speedup 1.0000x reference)
#include <cuda_runtime.h>
#include <cuda_bf16.h>
#include <cstdint>

#define NND 50000
#define EDG 800000
#define NTILES 391
#define SAPAD 136          // padded k-stride in bf16 (272B = 17x16B, 4-bank shift/row)
#define NSCB 196           // ceil(50000/256) scan blocks

// ---------------- scratch ----------------------------------------------------
__device__ float g_u[NND * 128];               // masked PReLU(x)
__device__ float g_U1[NND * 128];              // u + sum of u[src] over in-edges
__device__ float g_S[NND * 9];                 // sum of edge_attr over in-edges
__device__ float g_z[NND * 256];               // pre-BN hidden
__device__ float g_P[9 * 256];                 // W_e @ W1_bot
__device__ float g_q1[256];                    // b_e @ W1_bot
__device__ float g_cs[256];                    // column sums of z
__device__ float g_cq[256];                    // column sums of z^2
__device__ float g_a[256];                     // BN scale
__device__ float g_bb[256];                    // BN shift
__device__ __align__(16) __nv_bfloat16 g_Bz[2 * 256 * SAPAD];   // Wfold^T hi/lo planes
__device__ __align__(16) __nv_bfloat16 g_Bo[4 * 128 * SAPAD];   // W2^T [hi/lo][kc] planes
// CSR scratch
__device__ int g_cnt[NND];
__device__ int g_offp[NND];
__device__ int g_bs[NSCB];
__device__ int g_bo[NSCB + 1];
__device__ int g_off[NND + 1];
__device__ int g_cur[NND];
__device__ int g_srcs[EDG];
__device__ int g_eids[EDG];

// ---------------- helpers -----------------------------------------------------
__device__ __forceinline__ uint32_t smem_u32(const void* p) {
    uint32_t a;
    asm("{ .reg .u64 t; cvta.to.shared.u64 t, %1; cvt.u32.u64 %0, t; }" : "=r"(a) : "l"(p));
    return a;
}
__device__ __forceinline__ void ldsm4(uint32_t& r0, uint32_t& r1, uint32_t& r2, uint32_t& r3,
                                      uint32_t addr) {
    asm volatile("ldmatrix.sync.aligned.m8n8.x4.shared.b16 {%0,%1,%2,%3}, [%4];"
                 : "=r"(r0), "=r"(r1), "=r"(r2), "=r"(r3) : "r"(addr));
}
__device__ __forceinline__ void mma_bf16(float* c, const uint32_t* a, uint32_t b0, uint32_t b1) {
    asm volatile(
        "mma.sync.aligned.m16n8k16.row.col.f32.bf16.bf16.f32 "
        "{%0,%1,%2,%3}, {%4,%5,%6,%7}, {%8,%9}, {%0,%1,%2,%3};"
        : "+f"(c[0]), "+f"(c[1]), "+f"(c[2]), "+f"(c[3])
        : "r"(a[0]), "r"(a[1]), "r"(a[2]), "r"(a[3]), "r"(b0), "r"(b1));
}
__device__ __forceinline__ void split_store(__nv_bfloat16* hi, __nv_bfloat16* lo,
                                            int idx, float4 g) {
    __nv_bfloat16 hx = __float2bfloat16(g.x), hy = __float2bfloat16(g.y);
    __nv_bfloat16 hz = __float2bfloat16(g.z), hw = __float2bfloat16(g.w);
    __nv_bfloat16 lx = __float2bfloat16(g.x - __bfloat162float(hx));
    __nv_bfloat16 ly = __float2bfloat16(g.y - __bfloat162float(hy));
    __nv_bfloat16 lz = __float2bfloat16(g.z - __bfloat162float(hz));
    __nv_bfloat16 lw = __float2bfloat16(g.w - __bfloat162float(hw));
    uint2 h, l;
    h.x = ((uint32_t)__bfloat16_as_ushort(hy) << 16) | __bfloat16_as_ushort(hx);
    h.y = ((uint32_t)__bfloat16_as_ushort(hw) << 16) | __bfloat16_as_ushort(hz);
    l.x = ((uint32_t)__bfloat16_as_ushort(ly) << 16) | __bfloat16_as_ushort(lx);
    l.y = ((uint32_t)__bfloat16_as_ushort(lw) << 16) | __bfloat16_as_ushort(lz);
    *(uint2*)&hi[idx] = h;
    *(uint2*)&lo[idx] = l;
}
__device__ __forceinline__ uint32_t pack_bf16(float a, float b) {
    return ((uint32_t)__bfloat16_as_ushort(__float2bfloat16(b)) << 16) |
           __bfloat16_as_ushort(__float2bfloat16(a));
}

// ---------------- kernel 1: u = PReLU(x) -------------------------------------
__global__ void __launch_bounds__(256) prep_kernel(const float* __restrict__ x,
                                                   const float* __restrict__ pa) {
    const float a = *pa;
    size_t i = (size_t)blockIdx.x * 256 + threadIdx.x;
    if (i >= (size_t)NND * 32) return;
    float4 g = *(const float4*)&x[i * 4];
    g.x = g.x >= 0.f ? g.x : a * g.x;
    g.y = g.y >= 0.f ? g.y : a * g.y;
    g.z = g.z >= 0.f ? g.z : a * g.z;
    g.w = g.w >= 0.f ? g.w : a * g.w;
    *(float4*)&g_u[i * 4] = g;
}

// ---------------- kernel 2: zero masked rows ---------------------------------
__global__ void mask_kernel(const int* __restrict__ idx, int n) {
    int i = blockIdx.x;
    if (i >= n) return;
    unsigned v = (unsigned)idx[i];
    if (v < NND)
        *(float4*)&g_u[(size_t)v * 128 + threadIdx.x * 4] =
            make_float4(0.f, 0.f, 0.f, 0.f);
}

// ---------------- CSR build ---------------------------------------------------
__global__ void __launch_bounds__(256) hist_kernel(const int* __restrict__ ei) {
    int e = blockIdx.x * 256 + threadIdx.x;
    if (e >= EDG) return;
    unsigned s = (unsigned)ei[e];
    unsigned d = (unsigned)ei[EDG + e];
    if (s >= NND || d >= NND) return;
    atomicAdd(&g_cnt[d], 1);
}

__global__ void __launch_bounds__(256) scan1_kernel() {
    __shared__ int s[256];
    int t = threadIdx.x;
    int idx = blockIdx.x * 256 + t;
    int v = (idx < NND) ? g_cnt[idx] : 0;
    int val = v;
    s[t] = val;
    __syncthreads();
#pragma unroll
    for (int off = 1; off < 256; off <<= 1) {
        int add = (t >= off) ? s[t - off] : 0;
        __syncthreads();
        val += add;
        s[t] = val;
        __syncthreads();
    }
    if (idx < NND) g_offp[idx] = val - v;       // exclusive
    if (t == 255) g_bs[blockIdx.x] = val;       // block total
}

__global__ void __launch_bounds__(256) scan2_kernel() {
    __shared__ int s[256];
    int t = threadIdx.x;
    int v = (t < NSCB) ? g_bs[t] : 0;
    int val = v;
    s[t] = val;
    __syncthreads();
#pragma unroll
    for (int off = 1; off < 256; off <<= 1) {
        int add = (t >= off) ? s[t - off] : 0;
        __syncthreads();
        val += add;
        s[t] = val;
        __syncthreads();
    }
    if (t < NSCB) g_bo[t] = val - v;            // exclusive
    if (t == 255) g_bo[NSCB] = val;             // grand total
}

__global__ void __launch_bounds__(256) scan3_kernel() {
    int idx = blockIdx.x * 256 + threadIdx.x;
    if (idx < NND) {
        int o = g_offp[idx] + g_bo[blockIdx.x];
        g_off[idx] = o;
        g_cur[idx] = o;
    }
    if (idx == 0) g_off[NND] = g_bo[NSCB];
}

__global__ void __launch_bounds__(256) fill_kernel(const int* __restrict__ ei) {
    int e = blockIdx.x * 256 + threadIdx.x;
    if (e >= EDG) return;
    unsigned s = (unsigned)ei[e];
    unsigned d = (unsigned)ei[EDG + e];
    if (s >= NND || d >= NND) return;
    int p = atomicAdd(&g_cur[d], 1);
    g_srcs[p] = (int)s;
    g_eids[p] = e;
}

// ---------------- aggregate: U1[v] = u[v] + sum u[src]; S[v] = sum ea --------
__global__ void __launch_bounds__(256) aggregate_kernel(const float* __restrict__ ea) {
    int w = (int)((blockIdx.x * 256u + threadIdx.x) >> 5);
    int lane = threadIdx.x & 31;
    if (w >= NND) return;
    int nb = g_off[w], ne = g_off[w + 1];
    float4 acc = *(const float4*)&g_u[(size_t)w * 128 + lane * 4];
    float sa = 0.f;
    int i = nb;
    for (; i + 4 <= ne; i += 4) {
        int s0 = g_srcs[i], s1 = g_srcs[i + 1], s2 = g_srcs[i + 2], s3 = g_srcs[i + 3];
        float4 a = *(const float4*)&g_u[(size_t)s0 * 128 + lane * 4];
        float4 b = *(const float4*)&g_u[(size_t)s1 * 128 + lane * 4];
        float4 c = *(const float4*)&g_u[(size_t)s2 * 128 + lane * 4];
        float4 d = *(const float4*)&g_u[(size_t)s3 * 128 + lane * 4];
        acc.x += a.x + b.x + c.x + d.x;
        acc.y += a.y + b.y + c.y + d.y;
        acc.z += a.z + b.z + c.z + d.z;
        acc.w += a.w + b.w + c.w + d.w;
        if (lane < 9) {
            int e0 = g_eids[i], e1 = g_eids[i + 1], e2 = g_eids[i + 2], e3 = g_eids[i + 3];
            sa += ea[(size_t)e0 * 9 + lane] + ea[(size_t)e1 * 9 + lane]
                + ea[(size_t)e2 * 9 + lane] + ea[(size_t)e3 * 9 + lane];
        }
    }
    for (; i < ne; i++) {
        int s0 = g_srcs[i];
        float4 a = *(const float4*)&g_u[(size_t)s0 * 128 + lane * 4];
        acc.x += a.x; acc.y += a.y; acc.z += a.z; acc.w += a.w;
        if (lane < 9) sa += ea[(size_t)g_eids[i] * 9 + lane];
    }
    *(float4*)&g_U1[(size_t)w * 128 + lane * 4] = acc;
    if (lane < 9) g_S[(size_t)w * 9 + lane] = sa;
}

// ---------------- merged weight prep: blocks 0-7 fold_bz, 8-15 fold_bo, 16-25 precomp
__global__ void __launch_bounds__(256) weights_kernel(const float* __restrict__ Wenc,
                                                      const float* __restrict__ W1,
                                                      const float* __restrict__ W2,
                                                      const float* __restrict__ We,
                                                      const float* __restrict__ be) {
    __shared__ float ws[32 * 128];
    const int b = blockIdx.x;
    if (b < 8) {
        // fold_bz: Wfold^T hi/lo planes, 16 k-rows per block
        const int k0 = b * 16, c = threadIdx.x;
        for (int i = threadIdx.x; i < 512; i += 256)
            ((float4*)ws)[i] = ((const float4*)(Wenc + k0 * 128))[i];
        __syncthreads();
        float acc[16];
#pragma unroll
        for (int r = 0; r < 16; r++) acc[r] = 0.f;
        for (int m = 0; m < 128; m++) {
            float w1 = W1[m * 256 + c];
#pragma unroll
            for (int r = 0; r < 16; r++) acc[r] += ws[r * 128 + m] * w1;
        }
        uint32_t h[8], l[8];
#pragma unroll
        for (int r = 0; r < 8; r++) {
            float a0 = acc[2 * r], a1 = acc[2 * r + 1];
            float h0 = __bfloat162float(__float2bfloat16(a0));
            float h1 = __bfloat162float(__float2bfloat16(a1));
            h[r] = pack_bf16(a0, a1);
            l[r] = pack_bf16(a0 - h0, a1 - h1);
        }
        uint4* ph = (uint4*)&g_Bz[c * SAPAD + k0];
        uint4* pl = (uint4*)&g_Bz[256 * SAPAD + c * SAPAD + k0];
        ph[0] = make_uint4(h[0], h[1], h[2], h[3]);
        ph[1] = make_uint4(h[4], h[5], h[6], h[7]);
        pl[0] = make_uint4(l[0], l[1], l[2], l[3]);
        pl[1] = make_uint4(l[4], l[5], l[6], l[7]);
    } else if (b < 16) {
        // fold_bo: W2^T hi/lo planes, 32 k-rows per block
        const int k0 = (b - 8) * 32;
        const int kc = k0 >> 7, kk0 = k0 & 127;
        for (int i = threadIdx.x; i < 1024; i += 256)
            ((float4*)ws)[i] = ((const float4*)(W2 + k0 * 128))[i];
        __syncthreads();
        const int n = threadIdx.x >> 1, kl0 = (threadIdx.x & 1) * 16;
        uint32_t h[8], l[8];
#pragma unroll
        for (int q = 0; q < 8; q++) {
            float a0 = ws[(kl0 + 2 * q) * 128 + n];
            float a1 = ws[(kl0 + 2 * q + 1) * 128 + n];
            float h0 = __bfloat162float(__float2bfloat16(a0));
            float h1 = __bfloat162float(__float2bfloat16(a1));
            h[q] = pack_bf16(a0, a1);
            l[q] = pack_bf16(a0 - h0, a1 - h1);
        }
        uint4* ph = (uint4*)&g_Bo[(0 * 2 + kc) * 128 * SAPAD + n * SAPAD + kk0 + kl0];
        uint4* pl = (uint4*)&g_Bo[(1 * 2 + kc) * 128 * SAPAD + n * SAPAD + kk0 + kl0];
        ph[0] = make_uint4(h[0], h[1], h[2], h[3]);
        ph[1] = make_uint4(h[4], h[5], h[6], h[7]);
        pl[0] = make_uint4(l[0], l[1], l[2], l[3]);
        pl[1] = make_uint4(l[4], l[5], l[6], l[7]);
    } else {
        // precomp: P = W_e@W1_bot (16-24), q1 = b_e@W1_bot (25)
        const int j = b - 16, c = threadIdx.x;
        if (c < 128) ws[c] = (j < 9) ? We[j * 128 + c] : be[c];
        __syncthreads();
        float acc = 0.f;
#pragma unroll 8
        for (int m = 0; m < 128; m++) acc += ws[m] * W1[(128 + m) * 256 + c];
        if (j < 9) g_P[j * 256 + c] = acc;
        else       g_q1[c] = acc;
    }
}

// ---------------- kernel 5: HMMA gemm_z (512 threads, 16 warps 4Mx4N) --------
#define ZA_HI 0
#define ZA_LO 34816
#define ZB    69632
#define ZP    208896
#define ZQ1   218112
#define ZPC   219136
#define ZSS   220160
#define ZCS   226304
#define ZCQ   227328
#define ZSMEM 228352

__global__ void __launch_bounds__(512, 1) gemm_z_tc(const float* __restrict__ b1) {
    extern __shared__ __align__(16) unsigned char sm[];
    const uint32_t sbase = smem_u32(sm);
    const int tid = threadIdx.x, w = tid >> 5, lid = tid & 31;
    const int wm = w >> 2, wn = w & 3;
    const int rowBase = blockIdx.x * 128;
    float* Psm = (float*)(sm + ZP);
    float* Q1s = (float*)(sm + ZQ1);
    float* PCs = (float*)(sm + ZPC);
    float* Ssm = (float*)(sm + ZSS);
    float* CSs = (float*)(sm + ZCS);
    float* CQs = (float*)(sm + ZCQ);

    for (int i = tid; i < 2304; i += 512) Psm[i] = g_P[i];
    if (tid < 256) {
        Q1s[tid] = g_q1[tid];
        PCs[tid] = g_P[7 * 256 + tid] + b1[tid];
        CSs[tid] = 0.f;
        CQs[tid] = 0.f;
    }
    for (int i = tid; i < 1280; i += 512) {
        int r = i / 10, j = i % 10;
        int grow = rowBase + r;
        float v = 0.f;
        if (grow < NND)
            v = (j < 9) ? g_S[(size_t)grow * 9 + j]
                        : (float)(g_off[grow + 1] - g_off[grow]);
        Ssm[r * 12 + j] = v;
    }
    // stage A hi/lo: 512 threads, r = tid>>2, 32-col chunk
    {
        int r = tid >> 2, ch = (tid & 3) * 32;
        int grow = rowBase + r;
        __nv_bfloat16* ah = (__nv_bfloat16*)(sm + ZA_HI);
        __nv_bfloat16* al = (__nv_bfloat16*)(sm + ZA_LO);
        if (grow < NND) {
            const float* src = &g_U1[(size_t)grow * 128 + ch];
#pragma unroll
            for (int j = 0; j < 8; j++)
                split_store(ah, al, r * SAPAD + ch + j * 4, *(const float4*)&src[j * 4]);
        } else {
            float4 zz = make_float4(0.f, 0.f, 0.f, 0.f);
#pragma unroll
            for (int j = 0; j < 8; j++) split_store(ah, al, r * SAPAD + ch + j * 4, zz);
        }
    }
    for (int i = tid * 16; i < 139264; i += 512 * 16)
        *(float4*)(sm + ZB + i) = *(const float4*)((const unsigned char*)g_Bz + i);
    __syncthreads();

    float acc[2][8][4];
#pragma unroll
    for (int m = 0; m < 2; m++)
#pragma unroll
        for (int n = 0; n < 8; n++)
#pragma unroll
            for (int e = 0; e < 4; e++) acc[m][n][e] = 0.f;

    const uint32_t a_lane = (uint32_t)((((lid & 7) + 8 * ((lid >> 3) & 1)) * SAPAD + 8 * (lid >> 4)) * 2);
    const uint32_t b_lane = (uint32_t)((((lid & 7) + 8 * (lid >> 4)) * SAPAD + 8 * ((lid >> 3) & 1)) * 2);
    const uint32_t a_mbase = (uint32_t)(wm * 32 * SAPAD) * 2;
    const uint32_t b_nbase = (uint32_t)(wn * 64 * SAPAD) * 2;

#pragma unroll
    for (int t = 0; t < 3; t++) {
        uint32_t abase = sbase + (t == 2 ? ZA_LO : ZA_HI) + a_lane + a_mbase;
        uint32_t bbase = sbase + ZB + (t == 1 ? 69632u : 0u) + b_lane + b_nbase;
#pragma unroll
        for (int kt = 0; kt < 8; kt++) {
            uint32_t k2 = kt * 32;
            uint32_t af[2][4];
#pragma unroll
            for (int mt = 0; mt < 2; mt++)
                ldsm4(af[mt][0], af[mt][1], af[mt][2], af[mt][3],
                      abase + mt * (16 * SAPAD * 2) + k2);
            uint32_t bf[4][4];
#pragma unroll
            for (int i = 0; i < 4; i++)
                ldsm4(bf[i][0], bf[i][1], bf[i][2], bf[i][3],
                      bbase + i * (16 * SAPAD * 2) + k2);
#pragma unroll
            for (int mt = 0; mt < 2; mt++)
#pragma unroll
                for (int i = 0; i < 4; i++) {
                    mma_bf16(acc[mt][2 * i + 0], af[mt], bf[i][0], bf[i][1]);
                    mma_bf16(acc[mt][2 * i + 1], af[mt], bf[i][2], bf[i][3]);
                }
        }
    }

    // epilogue
    const int gid = lid >> 2, tig = lid & 3;
    float colS[16], colQ[16];
#pragma unroll
    for (int e = 0; e < 16; e++) { colS[e] = 0.f; colQ[e] = 0.f; }
#pragma unroll
    for (int mt = 0; mt < 2; mt++) {
        int r0 = wm * 32 + mt * 16 + gid, r1 = r0 + 8;
        int gr0 = rowBase + r0, gr1 = rowBase + r1;
        bool v0 = gr0 < NND, v1 = gr1 < NND;
        float s0[10], s1[10];
#pragma unroll
        for (int j = 0; j < 10; j++) { s0[j] = Ssm[r0 * 12 + j]; s1[j] = Ssm[r1 * 12 + j]; }
        float d0 = s0[9] + 1.f, d1v = s1[9] + 1.f;
#pragma unroll
        for (int nt = 0; nt < 8; nt++) {
            int c0 = wn * 64 + nt * 8 + 2 * tig, c1 = c0 + 1;
            float v00 = acc[mt][nt][0] + d0 * Q1s[c0] + PCs[c0];
            float v01 = acc[mt][nt][1] + d0 * Q1s[c1] + PCs[c1];
            float v10 = acc[mt][nt][2] + d1v * Q1s[c0] + PCs[c0];
            float v11 = acc[mt][nt][3] + d1v * Q1s[c1] + PCs[c1];
#pragma unroll
            for (int j = 0; j < 9; j++) {
                float p0 = Psm[j * 256 + c0], p1 = Psm[j * 256 + c1];
                v00 += s0[j] * p0; v01 += s0[j] * p1;
                v10 += s1[j] * p0; v11 += s1[j] * p1;
            }
            if (v0) {
                *(float2*)&g_z[(size_t)gr0 * 256 + c0] = make_float2(v00, v01);
                colS[nt * 2] += v00; colQ[nt * 2] += v00 * v00;
                colS[nt * 2 + 1] += v01; colQ[nt * 2 + 1] += v01 * v01;
            }
            if (v1) {
                *(float2*)&g_z[(size_t)gr1 * 256 + c0] = make_float2(v10, v11);
                colS[nt * 2] += v10; colQ[nt * 2] += v10 * v10;
                colS[nt * 2 + 1] += v11; colQ[nt * 2 + 1] += v11 * v11;
            }
        }
    }
    // reduce across gid (lanes tig, tig+4, ..., tig+28 share columns)
#pragma unroll
    for (int e = 0; e < 16; e++) {
#pragma unroll
        for (int off = 4; off < 32; off <<= 1) {
            colS[e] += __shfl_xor_sync(0xffffffffu, colS[e], off);
            colQ[e] += __shfl_xor_sync(0xffffffffu, colQ[e], off);
        }
    }
    if (gid == 0) {
#pragma unroll
        for (int nt = 0; nt < 8; nt++) {
#pragma unroll
            for (int e = 0; e < 2; e++) {
                int c = wn * 64 + nt * 8 + 2 * tig + e;
                atomicAdd(&CSs[c], colS[nt * 2 + e]);
                atomicAdd(&CQs[c], colQ[nt * 2 + e]);
            }
        }
    }
    __syncthreads();
    if (tid < 256) {
        atomicAdd(&g_cs[tid], CSs[tid]);
        atomicAdd(&g_cq[tid], CQs[tid]);
    }
}

// ---------------- kernel 6: BN finalize --------------------------------------
__global__ void bn_kernel(const float* __restrict__ gamma,
                          const float* __restrict__ beta) {
    int c = threadIdx.x;
    const float invN = 1.f / (float)NND;
    float m = g_cs[c] * invN;
    float var = g_cq[c] * invN - m * m;
    float av = gamma[c] * rsqrtf(var + 1e-5f);
    g_a[c] = av;
    g_bb[c] = beta[c] - m * av;
}

// ---------------- kernel 7: HMMA gemm_o (512 threads, 16 warps 4Mx4N) --------
#define OA_HI 0
#define OA_LO 34816
#define OB    69632
#define OSA   208896
#define OSB   209920
#define OB2   210944
#define OSMEM 211456

__global__ void __launch_bounds__(512, 1) gemm_o_tc(const float* __restrict__ b2,
                                                    float* __restrict__ out) {
    extern __shared__ __align__(16) unsigned char sm[];
    const uint32_t sbase = smem_u32(sm);
    const int tid = threadIdx.x, w = tid >> 5, lid = tid & 31;
    const int wm = w >> 2, wn = w & 3;
    const int rowBase = blockIdx.x * 128;
    float* SAs = (float*)(sm + OSA);
    float* SBs = (float*)(sm + OSB);
    float* B2s = (float*)(sm + OB2);
    if (tid < 256) { SAs[tid] = g_a[tid]; SBs[tid] = g_bb[tid]; }
    if (tid < 128) B2s[tid] = b2[tid];
    for (int i = tid * 16; i < 139264; i += 512 * 16)
        *(float4*)(sm + OB + i) = *(const float4*)((const unsigned char*)g_Bo + i);

    float acc[2][4][4];
#pragma unroll
    for (int m = 0; m < 2; m++)
#pragma unroll
        for (int n = 0; n < 4; n++)
#pragma unroll
            for (int e = 0; e < 4; e++) acc[m][n][e] = 0.f;

    const uint32_t a_lane = (uint32_t)((((lid & 7) + 8 * ((lid >> 3) & 1)) * SAPAD + 8 * (lid >> 4)) * 2);
    const uint32_t b_lane = (uint32_t)((((lid & 7) + 8 * (lid >> 4)) * SAPAD + 8 * ((lid >> 3) & 1)) * 2);
    const uint32_t a_mbase = (uint32_t)(wm * 32 * SAPAD) * 2;
    const uint32_t b_nbase = (uint32_t)(wn * 32 * SAPAD) * 2;

    for (int kc = 0; kc < 2; kc++) {
        __syncthreads();
        {
            int r = tid >> 2, ch = (tid & 3) * 32;
            int grow = rowBase + r;
            __nv_bfloat16* ah = (__nv_bfloat16*)(sm + OA_HI);
            __nv_bfloat16* al = (__nv_bfloat16*)(sm + OA_LO);
            if (grow < NND) {
                const float* src = &g_z[(size_t)grow * 256 + kc * 128 + ch];
#pragma unroll
                for (int j = 0; j < 8; j++) {
                    float4 g = *(const float4*)&src[j * 4];
                    int c0 = kc * 128 + ch + j * 4;
                    g.x = fmaxf(g.x * SAs[c0 + 0] + SBs[c0 + 0], 0.f);
                    g.y = fmaxf(g.y * SAs[c0 + 1] + SBs[c0 + 1], 0.f);
                    g.z = fmaxf(g.z * SAs[c0 + 2] + SBs[c0 + 2], 0.f);
                    g.w = fmaxf(g.w * SAs[c0 + 3] + SBs[c0 + 3], 0.f);
                    split_store(ah, al, r * SAPAD + ch + j * 4, g);
                }
            } else {
                float4 zz = make_float4(0.f, 0.f, 0.f, 0.f);
#pragma unroll
                for (int j = 0; j < 8; j++) split_store(ah, al, r * SAPAD + ch + j * 4, zz);
            }
        }
        __syncthreads();
#pragma unroll
        for (int t = 0; t < 3; t++) {
            uint32_t abase = sbase + (t == 2 ? OA_LO : OA_HI) + a_lane + a_mbase;
            uint32_t bbase = sbase + OB + (uint32_t)(((t == 1 ? 2 : 0) + kc) * 34816)
                           + b_lane + b_nbase;
#pragma unroll
            for (int kt = 0; kt < 8; kt++) {
                uint32_t k2 = kt * 32;
                uint32_t af[2][4];
#pragma unroll
                for (int mt = 0; mt < 2; mt++)
                    ldsm4(af[mt][0], af[mt][1], af[mt][2], af[mt][3],
                          abase + mt * (16 * SAPAD * 2) + k2);
                uint32_t bf[2][4];
#pragma unroll
                for (int i = 0; i < 2; i++)
                    ldsm4(bf[i][0], bf[i][1], bf[i][2], bf[i][3],
                          bbase + i * (16 * SAPAD * 2) + k2);
#pragma unroll
                for (int mt = 0; mt < 2; mt++)
#pragma unroll
                    for (int i = 0; i < 2; i++) {
                        mma_bf16(acc[mt][2 * i + 0], af[mt], bf[i][0], bf[i][1]);
                        mma_bf16(acc[mt][2 * i + 1], af[mt], bf[i][2], bf[i][3]);
                    }
            }
        }
    }

    const int gid = lid >> 2, tig = lid & 3;
#pragma unroll
    for (int mt = 0; mt < 2; mt++) {
        int r0 = wm * 32 + mt * 16 + gid, r1 = r0 + 8;
        int gr0 = rowBase + r0, gr1 = rowBase + r1;
#pragma unroll
        for (int nt = 0; nt < 4; nt++) {
            int c0 = wn * 32 + nt * 8 + 2 * tig;
            if (gr0 < NND)
                *(float2*)&out[(size_t)gr0 * 128 + c0] =
                    make_float2(acc[mt][nt][0] + B2s[c0], acc[mt][nt][1] + B2s[c0 + 1]);
            if (gr1 < NND)
                *(float2*)&out[(size_t)gr1 * 128 + c0] =
                    make_float2(acc[mt][nt][2] + B2s[c0], acc[mt][nt][3] + B2s[c0 + 1]);
        }
    }
}

// ---------------- launch ----------------------------------------------------
extern "C" void kernel_launch(void* const* d_in, const int* in_sizes, int n_in,
                              void* d_out, int out_size) {
    const float* x     = (const float*)d_in[0];
    const int*   ei    = (const int*)d_in[1];
    const float* ea    = (const float*)d_in[2];
    const int*   mask  = (const int*)d_in[3];
    const float* pa    = (const float*)d_in[4];
    const float* Wenc  = (const float*)d_in[5];
    const float* We    = (const float*)d_in[6];
    const float* be    = (const float*)d_in[7];
    const float* W1    = (const float*)d_in[8];
    const float* b1    = (const float*)d_in[9];
    const float* gamma = (const float*)d_in[10];
    const float* beta  = (const float*)d_in[11];
    const float* W2    = (const float*)d_in[12];
    const float* b2    = (const float*)d_in[13];
    float*       out   = (float*)d_out;
    const int nmask = in_sizes[3];

    cudaFuncSetAttribute(gemm_z_tc, cudaFuncAttributeMaxDynamicSharedMemorySize, ZSMEM);
    cudaFuncSetAttribute(gemm_o_tc, cudaFuncAttributeMaxDynamicSharedMemorySize, OSMEM);

    void *pcnt, *pcs, *pcq;
    cudaGetSymbolAddress(&pcnt, g_cnt);
    cudaGetSymbolAddress(&pcs, g_cs);
    cudaGetSymbolAddress(&pcq, g_cq);
    cudaMemsetAsync(pcnt, 0, sizeof(int) * NND, 0);
    cudaMemsetAsync(pcs, 0, sizeof(float) * 256, 0);
    cudaMemsetAsync(pcq, 0, sizeof(float) * 256, 0);

    prep_kernel<<<(NND * 32 + 255) / 256, 256>>>(x, pa);
    if (nmask > 0) mask_kernel<<<nmask, 32>>>(mask, nmask);
    hist_kernel<<<(EDG + 255) / 256, 256>>>(ei);
    scan1_kernel<<<NSCB, 256>>>();
    scan2_kernel<<<1, 256>>>();
    scan3_kernel<<<NSCB, 256>>>();
    fill_kernel<<<(EDG + 255) / 256, 256>>>(ei);
    aggregate_kernel<<<(NND * 32 + 255) / 256, 256>>>(ea);
    weights_kernel<<<26, 256>>>(Wenc, W1, W2, We, be);
    gemm_z_tc<<<NTILES, 512, ZSMEM>>>(b1);
    bn_kernel<<<1, 256>>>(gamma, beta);
    gemm_o_tc<<<NTILES, 512, OSMEM>>>(b2, out);
}

// round 12
// speedup vs baseline: 1.2677x; 1.2677x over previous
#include <cuda_runtime.h>
#include <cuda_bf16.h>
#include <cstdint>

#define NND 50000
#define EDG 800000
#define NTILES 391
#define SAPAD 136          // padded k-stride in bf16 (272B = 17x16B, 4-bank shift/row)
#define NSCB 196           // ceil(50000/256) scan blocks

// ---------------- scratch ----------------------------------------------------
__device__ float g_u[NND * 128];               // masked PReLU(x)
__device__ float g_U1[NND * 128];              // u + sum of u[src] over in-edges
__device__ float g_S[NND * 9];                 // sum of edge_attr over in-edges
__device__ float g_z[NND * 256];               // pre-BN hidden
__device__ float g_P[9 * 256];                 // W_e @ W1_bot
__device__ float g_q1[256];                    // b_e @ W1_bot
__device__ float g_cs[256];                    // column sums of z
__device__ float g_cq[256];                    // column sums of z^2
__device__ float g_a[256];                     // BN scale
__device__ float g_bb[256];                    // BN shift
__device__ __align__(16) __nv_bfloat16 g_Bz[2 * 256 * SAPAD];   // Wfold^T hi/lo planes
__device__ __align__(16) __nv_bfloat16 g_Bo[4 * 128 * SAPAD];   // W2^T [hi/lo][kc] planes
// CSR scratch
__device__ int g_cnt[NND];
__device__ int g_offp[NND];
__device__ int g_bs[NSCB];
__device__ int g_bo[NSCB + 1];
__device__ int g_off[NND + 1];
__device__ int g_cur[NND];
__device__ int g_srcs[EDG];
__device__ int g_eids[EDG];

// ---------------- helpers -----------------------------------------------------
__device__ __forceinline__ uint32_t smem_u32(const void* p) {
    uint32_t a;
    asm("{ .reg .u64 t; cvta.to.shared.u64 t, %1; cvt.u32.u64 %0, t; }" : "=r"(a) : "l"(p));
    return a;
}
__device__ __forceinline__ void ldsm4(uint32_t& r0, uint32_t& r1, uint32_t& r2, uint32_t& r3,
                                      uint32_t addr) {
    asm volatile("ldmatrix.sync.aligned.m8n8.x4.shared.b16 {%0,%1,%2,%3}, [%4];"
                 : "=r"(r0), "=r"(r1), "=r"(r2), "=r"(r3) : "r"(addr));
}
__device__ __forceinline__ void mma_bf16(float* c, const uint32_t* a, uint32_t b0, uint32_t b1) {
    asm volatile(
        "mma.sync.aligned.m16n8k16.row.col.f32.bf16.bf16.f32 "
        "{%0,%1,%2,%3}, {%4,%5,%6,%7}, {%8,%9}, {%0,%1,%2,%3};"
        : "+f"(c[0]), "+f"(c[1]), "+f"(c[2]), "+f"(c[3])
        : "r"(a[0]), "r"(a[1]), "r"(a[2]), "r"(a[3]), "r"(b0), "r"(b1));
}
__device__ __forceinline__ void split_store(__nv_bfloat16* hi, __nv_bfloat16* lo,
                                            int idx, float4 g) {
    __nv_bfloat16 hx = __float2bfloat16(g.x), hy = __float2bfloat16(g.y);
    __nv_bfloat16 hz = __float2bfloat16(g.z), hw = __float2bfloat16(g.w);
    __nv_bfloat16 lx = __float2bfloat16(g.x - __bfloat162float(hx));
    __nv_bfloat16 ly = __float2bfloat16(g.y - __bfloat162float(hy));
    __nv_bfloat16 lz = __float2bfloat16(g.z - __bfloat162float(hz));
    __nv_bfloat16 lw = __float2bfloat16(g.w - __bfloat162float(hw));
    uint2 h, l;
    h.x = ((uint32_t)__bfloat16_as_ushort(hy) << 16) | __bfloat16_as_ushort(hx);
    h.y = ((uint32_t)__bfloat16_as_ushort(hw) << 16) | __bfloat16_as_ushort(hz);
    l.x = ((uint32_t)__bfloat16_as_ushort(ly) << 16) | __bfloat16_as_ushort(lx);
    l.y = ((uint32_t)__bfloat16_as_ushort(lw) << 16) | __bfloat16_as_ushort(lz);
    *(uint2*)&hi[idx] = h;
    *(uint2*)&lo[idx] = l;
}
__device__ __forceinline__ uint32_t pack_bf16(float a, float b) {
    return ((uint32_t)__bfloat16_as_ushort(__float2bfloat16(b)) << 16) |
           __bfloat16_as_ushort(__float2bfloat16(a));
}

// ---------------- kernel 1: u = PReLU(x) -------------------------------------
__global__ void __launch_bounds__(256) prep_kernel(const float* __restrict__ x,
                                                   const float* __restrict__ pa) {
    const float a = *pa;
    size_t i = (size_t)blockIdx.x * 256 + threadIdx.x;
    if (i >= (size_t)NND * 32) return;
    float4 g = *(const float4*)&x[i * 4];
    g.x = g.x >= 0.f ? g.x : a * g.x;
    g.y = g.y >= 0.f ? g.y : a * g.y;
    g.z = g.z >= 0.f ? g.z : a * g.z;
    g.w = g.w >= 0.f ? g.w : a * g.w;
    *(float4*)&g_u[i * 4] = g;
}

// ---------------- kernel 2: zero masked rows ---------------------------------
__global__ void mask_kernel(const int* __restrict__ idx, int n) {
    int i = blockIdx.x;
    if (i >= n) return;
    unsigned v = (unsigned)idx[i];
    if (v < NND)
        *(float4*)&g_u[(size_t)v * 128 + threadIdx.x * 4] =
            make_float4(0.f, 0.f, 0.f, 0.f);
}

// ---------------- CSR build ---------------------------------------------------
__global__ void __launch_bounds__(256) hist_kernel(const int* __restrict__ ei) {
    int e = blockIdx.x * 256 + threadIdx.x;
    if (e >= EDG) return;
    unsigned s = (unsigned)ei[e];
    unsigned d = (unsigned)ei[EDG + e];
    if (s >= NND || d >= NND) return;
    atomicAdd(&g_cnt[d], 1);
}

__global__ void __launch_bounds__(256) scan1_kernel() {
    __shared__ int s[256];
    int t = threadIdx.x;
    int idx = blockIdx.x * 256 + t;
    int v = (idx < NND) ? g_cnt[idx] : 0;
    int val = v;
    s[t] = val;
    __syncthreads();
#pragma unroll
    for (int off = 1; off < 256; off <<= 1) {
        int add = (t >= off) ? s[t - off] : 0;
        __syncthreads();
        val += add;
        s[t] = val;
        __syncthreads();
    }
    if (idx < NND) g_offp[idx] = val - v;       // exclusive
    if (t == 255) g_bs[blockIdx.x] = val;       // block total
}

__global__ void __launch_bounds__(256) scan2_kernel() {
    __shared__ int s[256];
    int t = threadIdx.x;
    int v = (t < NSCB) ? g_bs[t] : 0;
    int val = v;
    s[t] = val;
    __syncthreads();
#pragma unroll
    for (int off = 1; off < 256; off <<= 1) {
        int add = (t >= off) ? s[t - off] : 0;
        __syncthreads();
        val += add;
        s[t] = val;
        __syncthreads();
    }
    if (t < NSCB) g_bo[t] = val - v;            // exclusive
    if (t == 255) g_bo[NSCB] = val;             // grand total
}

__global__ void __launch_bounds__(256) scan3_kernel() {
    int idx = blockIdx.x * 256 + threadIdx.x;
    if (idx < NND) {
        int o = g_offp[idx] + g_bo[blockIdx.x];
        g_off[idx] = o;
        g_cur[idx] = o;
    }
    if (idx == 0) g_off[NND] = g_bo[NSCB];
}

__global__ void __launch_bounds__(256) fill_kernel(const int* __restrict__ ei) {
    int e = blockIdx.x * 256 + threadIdx.x;
    if (e >= EDG) return;
    unsigned s = (unsigned)ei[e];
    unsigned d = (unsigned)ei[EDG + e];
    if (s >= NND || d >= NND) return;
    int p = atomicAdd(&g_cur[d], 1);
    g_srcs[p] = (int)s;
    g_eids[p] = e;
}

// ---------------- aggregate: U1[v] = u[v] + sum u[src]; S[v] = sum ea --------
__global__ void __launch_bounds__(256) aggregate_kernel(const float* __restrict__ ea) {
    int w = (int)((blockIdx.x * 256u + threadIdx.x) >> 5);
    int lane = threadIdx.x & 31;
    if (w >= NND) return;
    int nb = g_off[w], ne = g_off[w + 1];
    float4 acc = *(const float4*)&g_u[(size_t)w * 128 + lane * 4];
    float sa = 0.f;
    int i = nb;
    for (; i + 4 <= ne; i += 4) {
        int s0 = g_srcs[i], s1 = g_srcs[i + 1], s2 = g_srcs[i + 2], s3 = g_srcs[i + 3];
        float4 a = *(const float4*)&g_u[(size_t)s0 * 128 + lane * 4];
        float4 b = *(const float4*)&g_u[(size_t)s1 * 128 + lane * 4];
        float4 c = *(const float4*)&g_u[(size_t)s2 * 128 + lane * 4];
        float4 d = *(const float4*)&g_u[(size_t)s3 * 128 + lane * 4];
        acc.x += a.x + b.x + c.x + d.x;
        acc.y += a.y + b.y + c.y + d.y;
        acc.z += a.z + b.z + c.z + d.z;
        acc.w += a.w + b.w + c.w + d.w;
        if (lane < 9) {
            int e0 = g_eids[i], e1 = g_eids[i + 1], e2 = g_eids[i + 2], e3 = g_eids[i + 3];
            sa += ea[(size_t)e0 * 9 + lane] + ea[(size_t)e1 * 9 + lane]
                + ea[(size_t)e2 * 9 + lane] + ea[(size_t)e3 * 9 + lane];
        }
    }
    for (; i < ne; i++) {
        int s0 = g_srcs[i];
        float4 a = *(const float4*)&g_u[(size_t)s0 * 128 + lane * 4];
        acc.x += a.x; acc.y += a.y; acc.z += a.z; acc.w += a.w;
        if (lane < 9) sa += ea[(size_t)g_eids[i] * 9 + lane];
    }
    *(float4*)&g_U1[(size_t)w * 128 + lane * 4] = acc;
    if (lane < 9) g_S[(size_t)w * 9 + lane] = sa;
}

// ---------------- merged weight prep: blocks 0-7 fold_bz, 8-15 fold_bo, 16-25 precomp
__global__ void __launch_bounds__(256) weights_kernel(const float* __restrict__ Wenc,
                                                      const float* __restrict__ W1,
                                                      const float* __restrict__ W2,
                                                      const float* __restrict__ We,
                                                      const float* __restrict__ be) {
    __shared__ float ws[32 * 128];
    const int b = blockIdx.x;
    if (b < 8) {
        const int k0 = b * 16, c = threadIdx.x;
        for (int i = threadIdx.x; i < 512; i += 256)
            ((float4*)ws)[i] = ((const float4*)(Wenc + k0 * 128))[i];
        __syncthreads();
        float acc[16];
#pragma unroll
        for (int r = 0; r < 16; r++) acc[r] = 0.f;
        for (int m = 0; m < 128; m++) {
            float w1 = W1[m * 256 + c];
#pragma unroll
            for (int r = 0; r < 16; r++) acc[r] += ws[r * 128 + m] * w1;
        }
        uint32_t h[8], l[8];
#pragma unroll
        for (int r = 0; r < 8; r++) {
            float a0 = acc[2 * r], a1 = acc[2 * r + 1];
            float h0 = __bfloat162float(__float2bfloat16(a0));
            float h1 = __bfloat162float(__float2bfloat16(a1));
            h[r] = pack_bf16(a0, a1);
            l[r] = pack_bf16(a0 - h0, a1 - h1);
        }
        uint4* ph = (uint4*)&g_Bz[c * SAPAD + k0];
        uint4* pl = (uint4*)&g_Bz[256 * SAPAD + c * SAPAD + k0];
        ph[0] = make_uint4(h[0], h[1], h[2], h[3]);
        ph[1] = make_uint4(h[4], h[5], h[6], h[7]);
        pl[0] = make_uint4(l[0], l[1], l[2], l[3]);
        pl[1] = make_uint4(l[4], l[5], l[6], l[7]);
    } else if (b < 16) {
        const int k0 = (b - 8) * 32;
        const int kc = k0 >> 7, kk0 = k0 & 127;
        for (int i = threadIdx.x; i < 1024; i += 256)
            ((float4*)ws)[i] = ((const float4*)(W2 + k0 * 128))[i];
        __syncthreads();
        const int n = threadIdx.x >> 1, kl0 = (threadIdx.x & 1) * 16;
        uint32_t h[8], l[8];
#pragma unroll
        for (int q = 0; q < 8; q++) {
            float a0 = ws[(kl0 + 2 * q) * 128 + n];
            float a1 = ws[(kl0 + 2 * q + 1) * 128 + n];
            float h0 = __bfloat162float(__float2bfloat16(a0));
            float h1 = __bfloat162float(__float2bfloat16(a1));
            h[q] = pack_bf16(a0, a1);
            l[q] = pack_bf16(a0 - h0, a1 - h1);
        }
        uint4* ph = (uint4*)&g_Bo[(0 * 2 + kc) * 128 * SAPAD + n * SAPAD + kk0 + kl0];
        uint4* pl = (uint4*)&g_Bo[(1 * 2 + kc) * 128 * SAPAD + n * SAPAD + kk0 + kl0];
        ph[0] = make_uint4(h[0], h[1], h[2], h[3]);
        ph[1] = make_uint4(h[4], h[5], h[6], h[7]);
        pl[0] = make_uint4(l[0], l[1], l[2], l[3]);
        pl[1] = make_uint4(l[4], l[5], l[6], l[7]);
    } else {
        const int j = b - 16, c = threadIdx.x;
        if (c < 128) ws[c] = (j < 9) ? We[j * 128 + c] : be[c];
        __syncthreads();
        float acc = 0.f;
#pragma unroll 8
        for (int m = 0; m < 128; m++) acc += ws[m] * W1[(128 + m) * 256 + c];
        if (j < 9) g_P[j * 256 + c] = acc;
        else       g_q1[c] = acc;
    }
}

// ---------------- kernel 5: HMMA gemm_z (256 threads, A-hi reuse) ------------
#define ZA_HI 0
#define ZA_LO 34816
#define ZB    69632
#define ZP    208896
#define ZQ1   218112
#define ZPC   219136
#define ZSS   220160
#define ZCS   226304
#define ZCQ   227328
#define ZSMEM 228352

__global__ void __launch_bounds__(256, 1) gemm_z_tc(const float* __restrict__ b1) {
    extern __shared__ __align__(16) unsigned char sm[];
    const uint32_t sbase = smem_u32(sm);
    const int tid = threadIdx.x, w = tid >> 5, lid = tid & 31;
    const int rowBase = blockIdx.x * 128;
    float* Psm = (float*)(sm + ZP);
    float* Q1s = (float*)(sm + ZQ1);
    float* PCs = (float*)(sm + ZPC);
    float* Ssm = (float*)(sm + ZSS);
    float* CSs = (float*)(sm + ZCS);
    float* CQs = (float*)(sm + ZCQ);

    for (int i = tid; i < 2304; i += 256) Psm[i] = g_P[i];
    Q1s[tid] = g_q1[tid];
    PCs[tid] = g_P[7 * 256 + tid] + b1[tid];
    CSs[tid] = 0.f;
    CQs[tid] = 0.f;
    for (int i = tid; i < 1280; i += 256) {
        int r = i / 10, j = i % 10;
        int grow = rowBase + r;
        float v = 0.f;
        if (grow < NND)
            v = (j < 9) ? g_S[(size_t)grow * 9 + j]
                        : (float)(g_off[grow + 1] - g_off[grow]);
        Ssm[r * 12 + j] = v;
    }
    // stage A hi/lo
    {
        int r = tid >> 1, ch = (tid & 1) * 64;
        int grow = rowBase + r;
        __nv_bfloat16* ah = (__nv_bfloat16*)(sm + ZA_HI);
        __nv_bfloat16* al = (__nv_bfloat16*)(sm + ZA_LO);
        if (grow < NND) {
            const float* src = &g_U1[(size_t)grow * 128 + ch];
#pragma unroll
            for (int j = 0; j < 16; j++)
                split_store(ah, al, r * SAPAD + ch + j * 4, *(const float4*)&src[j * 4]);
        } else {
            float4 zz = make_float4(0.f, 0.f, 0.f, 0.f);
#pragma unroll
            for (int j = 0; j < 16; j++) split_store(ah, al, r * SAPAD + ch + j * 4, zz);
        }
    }
    for (int i = tid * 16; i < 139264; i += 256 * 16)
        *(float4*)(sm + ZB + i) = *(const float4*)((const unsigned char*)g_Bz + i);
    __syncthreads();

    float acc[8][4][4];
#pragma unroll
    for (int m = 0; m < 8; m++)
#pragma unroll
        for (int n = 0; n < 4; n++)
#pragma unroll
            for (int e = 0; e < 4; e++) acc[m][n][e] = 0.f;

    const uint32_t a_lane = (uint32_t)((((lid & 7) + 8 * ((lid >> 3) & 1)) * SAPAD + 8 * (lid >> 4)) * 2);
    const uint32_t b_lane = (uint32_t)((((lid & 7) + 8 * (lid >> 4)) * SAPAD + 8 * ((lid >> 3) & 1)) * 2);
    const uint32_t bb_hi = sbase + ZB + b_lane + (uint32_t)(w * 32 * SAPAD) * 2;
    const uint32_t bb_lo = bb_hi + 69632u;

    // pass 1: A-hi x (B-hi + B-lo), A-hi fragments loaded once per kt
#pragma unroll
    for (int kt = 0; kt < 8; kt++) {
        uint32_t k2 = kt * 32;
        uint32_t af[8][4];
#pragma unroll
        for (int mt = 0; mt < 8; mt++)
            ldsm4(af[mt][0], af[mt][1], af[mt][2], af[mt][3],
                  sbase + ZA_HI + a_lane + mt * (16 * SAPAD * 2) + k2);
        uint32_t bh0[4], bh1[4], bl0[4], bl1[4];
        ldsm4(bh0[0], bh0[1], bh0[2], bh0[3], bb_hi + k2);
        ldsm4(bh1[0], bh1[1], bh1[2], bh1[3], bb_hi + 16 * SAPAD * 2 + k2);
        ldsm4(bl0[0], bl0[1], bl0[2], bl0[3], bb_lo + k2);
        ldsm4(bl1[0], bl1[1], bl1[2], bl1[3], bb_lo + 16 * SAPAD * 2 + k2);
#pragma unroll
        for (int mt = 0; mt < 8; mt++) {
            mma_bf16(acc[mt][0], af[mt], bh0[0], bh0[1]);
            mma_bf16(acc[mt][1], af[mt], bh0[2], bh0[3]);
            mma_bf16(acc[mt][2], af[mt], bh1[0], bh1[1]);
            mma_bf16(acc[mt][3], af[mt], bh1[2], bh1[3]);
            mma_bf16(acc[mt][0], af[mt], bl0[0], bl0[1]);
            mma_bf16(acc[mt][1], af[mt], bl0[2], bl0[3]);
            mma_bf16(acc[mt][2], af[mt], bl1[0], bl1[1]);
            mma_bf16(acc[mt][3], af[mt], bl1[2], bl1[3]);
        }
    }
    // pass 2: A-lo x B-hi
#pragma unroll
    for (int kt = 0; kt < 8; kt++) {
        uint32_t k2 = kt * 32;
        uint32_t af[8][4];
#pragma unroll
        for (int mt = 0; mt < 8; mt++)
            ldsm4(af[mt][0], af[mt][1], af[mt][2], af[mt][3],
                  sbase + ZA_LO + a_lane + mt * (16 * SAPAD * 2) + k2);
        uint32_t bh0[4], bh1[4];
        ldsm4(bh0[0], bh0[1], bh0[2], bh0[3], bb_hi + k2);
        ldsm4(bh1[0], bh1[1], bh1[2], bh1[3], bb_hi + 16 * SAPAD * 2 + k2);
#pragma unroll
        for (int mt = 0; mt < 8; mt++) {
            mma_bf16(acc[mt][0], af[mt], bh0[0], bh0[1]);
            mma_bf16(acc[mt][1], af[mt], bh0[2], bh0[3]);
            mma_bf16(acc[mt][2], af[mt], bh1[0], bh1[1]);
            mma_bf16(acc[mt][3], af[mt], bh1[2], bh1[3]);
        }
    }

    // epilogue
    const int gid = lid >> 2, tig = lid & 3;
    float colS[8], colQ[8];
#pragma unroll
    for (int e = 0; e < 8; e++) { colS[e] = 0.f; colQ[e] = 0.f; }
#pragma unroll
    for (int mt = 0; mt < 8; mt++) {
        int r0 = mt * 16 + gid, r1 = r0 + 8;
        int gr0 = rowBase + r0, gr1 = rowBase + r1;
        bool v0 = gr0 < NND, v1 = gr1 < NND;
        float s0[10], s1[10];
#pragma unroll
        for (int j = 0; j < 10; j++) { s0[j] = Ssm[r0 * 12 + j]; s1[j] = Ssm[r1 * 12 + j]; }
        float d0 = s0[9] + 1.f, d1v = s1[9] + 1.f;
#pragma unroll
        for (int nt = 0; nt < 4; nt++) {
            int c0 = w * 32 + nt * 8 + 2 * tig, c1 = c0 + 1;
            float v00 = acc[mt][nt][0] + d0 * Q1s[c0] + PCs[c0];
            float v01 = acc[mt][nt][1] + d0 * Q1s[c1] + PCs[c1];
            float v10 = acc[mt][nt][2] + d1v * Q1s[c0] + PCs[c0];
            float v11 = acc[mt][nt][3] + d1v * Q1s[c1] + PCs[c1];
#pragma unroll
            for (int j = 0; j < 9; j++) {
                float p0 = Psm[j * 256 + c0], p1 = Psm[j * 256 + c1];
                v00 += s0[j] * p0; v01 += s0[j] * p1;
                v10 += s1[j] * p0; v11 += s1[j] * p1;
            }
            if (v0) {
                *(float2*)&g_z[(size_t)gr0 * 256 + c0] = make_float2(v00, v01);
                colS[nt * 2] += v00; colQ[nt * 2] += v00 * v00;
                colS[nt * 2 + 1] += v01; colQ[nt * 2 + 1] += v01 * v01;
            }
            if (v1) {
                *(float2*)&g_z[(size_t)gr1 * 256 + c0] = make_float2(v10, v11);
                colS[nt * 2] += v10; colQ[nt * 2] += v10 * v10;
                colS[nt * 2 + 1] += v11; colQ[nt * 2 + 1] += v11 * v11;
            }
        }
    }
#pragma unroll
    for (int nt = 0; nt < 4; nt++) {
#pragma unroll
        for (int e = 0; e < 2; e++) {
            int c = w * 32 + nt * 8 + 2 * tig + e;
            atomicAdd(&CSs[c], colS[nt * 2 + e]);
            atomicAdd(&CQs[c], colQ[nt * 2 + e]);
        }
    }
    __syncthreads();
    atomicAdd(&g_cs[tid], CSs[tid]);
    atomicAdd(&g_cq[tid], CQs[tid]);
}

// ---------------- kernel 6: BN finalize --------------------------------------
__global__ void bn_kernel(const float* __restrict__ gamma,
                          const float* __restrict__ beta) {
    int c = threadIdx.x;
    const float invN = 1.f / (float)NND;
    float m = g_cs[c] * invN;
    float var = g_cq[c] * invN - m * m;
    float av = gamma[c] * rsqrtf(var + 1e-5f);
    g_a[c] = av;
    g_bb[c] = beta[c] - m * av;
}

// ---------------- kernel 7: HMMA gemm_o (256 threads, A-hi reuse) ------------
#define OA_HI 0
#define OA_LO 34816
#define OB    69632
#define OSA   208896
#define OSB   209920
#define OB2   210944
#define OSMEM 211456

__global__ void __launch_bounds__(256, 1) gemm_o_tc(const float* __restrict__ b2,
                                                    float* __restrict__ out) {
    extern __shared__ __align__(16) unsigned char sm[];
    const uint32_t sbase = smem_u32(sm);
    const int tid = threadIdx.x, w = tid >> 5, lid = tid & 31;
    const int rowBase = blockIdx.x * 128;
    float* SAs = (float*)(sm + OSA);
    float* SBs = (float*)(sm + OSB);
    float* B2s = (float*)(sm + OB2);
    SAs[tid] = g_a[tid];
    SBs[tid] = g_bb[tid];
    if (tid < 128) B2s[tid] = b2[tid];
    for (int i = tid * 16; i < 139264; i += 256 * 16)
        *(float4*)(sm + OB + i) = *(const float4*)((const unsigned char*)g_Bo + i);

    float acc[4][4][4];
#pragma unroll
    for (int m = 0; m < 4; m++)
#pragma unroll
        for (int n = 0; n < 4; n++)
#pragma unroll
            for (int e = 0; e < 4; e++) acc[m][n][e] = 0.f;

    const uint32_t a_lane = (uint32_t)((((lid & 7) + 8 * ((lid >> 3) & 1)) * SAPAD + 8 * (lid >> 4)) * 2);
    const uint32_t b_lane = (uint32_t)((((lid & 7) + 8 * (lid >> 4)) * SAPAD + 8 * ((lid >> 3) & 1)) * 2);
    const uint32_t a_mbase = (uint32_t)((w >> 2) * 64 * SAPAD * 2);
    const uint32_t b_nbase = (uint32_t)((w & 3) * 32 * SAPAD * 2);

    for (int kc = 0; kc < 2; kc++) {
        __syncthreads();
        {
            int r = tid >> 1, ch = (tid & 1) * 64;
            int grow = rowBase + r;
            __nv_bfloat16* ah = (__nv_bfloat16*)(sm + OA_HI);
            __nv_bfloat16* al = (__nv_bfloat16*)(sm + OA_LO);
            if (grow < NND) {
                const float* src = &g_z[(size_t)grow * 256 + kc * 128 + ch];
#pragma unroll
                for (int j = 0; j < 16; j++) {
                    float4 g = *(const float4*)&src[j * 4];
                    int c0 = kc * 128 + ch + j * 4;
                    g.x = fmaxf(g.x * SAs[c0 + 0] + SBs[c0 + 0], 0.f);
                    g.y = fmaxf(g.y * SAs[c0 + 1] + SBs[c0 + 1], 0.f);
                    g.z = fmaxf(g.z * SAs[c0 + 2] + SBs[c0 + 2], 0.f);
                    g.w = fmaxf(g.w * SAs[c0 + 3] + SBs[c0 + 3], 0.f);
                    split_store(ah, al, r * SAPAD + ch + j * 4, g);
                }
            } else {
                float4 zz = make_float4(0.f, 0.f, 0.f, 0.f);
#pragma unroll
                for (int j = 0; j < 16; j++) split_store(ah, al, r * SAPAD + ch + j * 4, zz);
            }
        }
        __syncthreads();
        const uint32_t bb_hi = sbase + OB + (uint32_t)(kc * 34816) + b_lane + b_nbase;
        const uint32_t bb_lo = bb_hi + 2u * 34816u;
        // pass 1: A-hi x (B-hi + B-lo)
#pragma unroll
        for (int kt = 0; kt < 8; kt++) {
            uint32_t k2 = kt * 32;
            uint32_t af[4][4];
#pragma unroll
            for (int mt = 0; mt < 4; mt++)
                ldsm4(af[mt][0], af[mt][1], af[mt][2], af[mt][3],
                      sbase + OA_HI + a_lane + a_mbase + mt * (16 * SAPAD * 2) + k2);
            uint32_t bh0[4], bh1[4], bl0[4], bl1[4];
            ldsm4(bh0[0], bh0[1], bh0[2], bh0[3], bb_hi + k2);
            ldsm4(bh1[0], bh1[1], bh1[2], bh1[3], bb_hi + 16 * SAPAD * 2 + k2);
            ldsm4(bl0[0], bl0[1], bl0[2], bl0[3], bb_lo + k2);
            ldsm4(bl1[0], bl1[1], bl1[2], bl1[3], bb_lo + 16 * SAPAD * 2 + k2);
#pragma unroll
            for (int mt = 0; mt < 4; mt++) {
                mma_bf16(acc[mt][0], af[mt], bh0[0], bh0[1]);
                mma_bf16(acc[mt][1], af[mt], bh0[2], bh0[3]);
                mma_bf16(acc[mt][2], af[mt], bh1[0], bh1[1]);
                mma_bf16(acc[mt][3], af[mt], bh1[2], bh1[3]);
                mma_bf16(acc[mt][0], af[mt], bl0[0], bl0[1]);
                mma_bf16(acc[mt][1], af[mt], bl0[2], bl0[3]);
                mma_bf16(acc[mt][2], af[mt], bl1[0], bl1[1]);
                mma_bf16(acc[mt][3], af[mt], bl1[2], bl1[3]);
            }
        }
        // pass 2: A-lo x B-hi
#pragma unroll
        for (int kt = 0; kt < 8; kt++) {
            uint32_t k2 = kt * 32;
            uint32_t af[4][4];
#pragma unroll
            for (int mt = 0; mt < 4; mt++)
                ldsm4(af[mt][0], af[mt][1], af[mt][2], af[mt][3],
                      sbase + OA_LO + a_lane + a_mbase + mt * (16 * SAPAD * 2) + k2);
            uint32_t bh0[4], bh1[4];
            ldsm4(bh0[0], bh0[1], bh0[2], bh0[3], bb_hi + k2);
            ldsm4(bh1[0], bh1[1], bh1[2], bh1[3], bb_hi + 16 * SAPAD * 2 + k2);
#pragma unroll
            for (int mt = 0; mt < 4; mt++) {
                mma_bf16(acc[mt][0], af[mt], bh0[0], bh0[1]);
                mma_bf16(acc[mt][1], af[mt], bh0[2], bh0[3]);
                mma_bf16(acc[mt][2], af[mt], bh1[0], bh1[1]);
                mma_bf16(acc[mt][3], af[mt], bh1[2], bh1[3]);
            }
        }
    }

    const int gid = lid >> 2, tig = lid & 3;
#pragma unroll
    for (int mt = 0; mt < 4; mt++) {
        int r0 = (w >> 2) * 64 + mt * 16 + gid, r1 = r0 + 8;
        int gr0 = rowBase + r0, gr1 = rowBase + r1;
#pragma unroll
        for (int nt = 0; nt < 4; nt++) {
            int c0 = (w & 3) * 32 + nt * 8 + 2 * tig;
            if (gr0 < NND)
                *(float2*)&out[(size_t)gr0 * 128 + c0] =
                    make_float2(acc[mt][nt][0] + B2s[c0], acc[mt][nt][1] + B2s[c0 + 1]);
            if (gr1 < NND)
                *(float2*)&out[(size_t)gr1 * 128 + c0] =
                    make_float2(acc[mt][nt][2] + B2s[c0], acc[mt][nt][3] + B2s[c0 + 1]);
        }
    }
}

// ---------------- launch ----------------------------------------------------
extern "C" void kernel_launch(void* const* d_in, const int* in_sizes, int n_in,
                              void* d_out, int out_size) {
    const float* x     = (const float*)d_in[0];
    const int*   ei    = (const int*)d_in[1];
    const float* ea    = (const float*)d_in[2];
    const int*   mask  = (const int*)d_in[3];
    const float* pa    = (const float*)d_in[4];
    const float* Wenc  = (const float*)d_in[5];
    const float* We    = (const float*)d_in[6];
    const float* be    = (const float*)d_in[7];
    const float* W1    = (const float*)d_in[8];
    const float* b1    = (const float*)d_in[9];
    const float* gamma = (const float*)d_in[10];
    const float* beta  = (const float*)d_in[11];
    const float* W2    = (const float*)d_in[12];
    const float* b2    = (const float*)d_in[13];
    float*       out   = (float*)d_out;
    const int nmask = in_sizes[3];

    cudaFuncSetAttribute(gemm_z_tc, cudaFuncAttributeMaxDynamicSharedMemorySize, ZSMEM);
    cudaFuncSetAttribute(gemm_o_tc, cudaFuncAttributeMaxDynamicSharedMemorySize, OSMEM);

    void *pcnt, *pcs, *pcq;
    cudaGetSymbolAddress(&pcnt, g_cnt);
    cudaGetSymbolAddress(&pcs, g_cs);
    cudaGetSymbolAddress(&pcq, g_cq);
    cudaMemsetAsync(pcnt, 0, sizeof(int) * NND, 0);
    cudaMemsetAsync(pcs, 0, sizeof(float) * 256, 0);
    cudaMemsetAsync(pcq, 0, sizeof(float) * 256, 0);

    prep_kernel<<<(NND * 32 + 255) / 256, 256>>>(x, pa);
    if (nmask > 0) mask_kernel<<<nmask, 32>>>(mask, nmask);
    hist_kernel<<<(EDG + 255) / 256, 256>>>(ei);
    scan1_kernel<<<NSCB, 256>>>();
    scan2_kernel<<<1, 256>>>();
    scan3_kernel<<<NSCB, 256>>>();
    fill_kernel<<<(EDG + 255) / 256, 256>>>(ei);
    aggregate_kernel<<<(NND * 32 + 255) / 256, 256>>>(ea);
    weights_kernel<<<26, 256>>>(Wenc, W1, W2, We, be);
    gemm_z_tc<<<NTILES, 256, ZSMEM>>>(b1);
    bn_kernel<<<1, 256>>>(gamma, beta);
    gemm_o_tc<<<NTILES, 256, OSMEM>>>(b2, out);
}

// round 13
// speedup vs baseline: 1.3934x; 1.0992x over previous
#include <cuda_runtime.h>
#include <cuda_fp16.h>
#include <cstdint>

#define NND 50000
#define EDG 800000
#define NTILES 391
#define SAPAD 136          // padded k-stride in fp16 (272B = 17x16B, 4-bank shift/row)
#define NSCB 196           // ceil(50000/256) scan blocks

// ---------------- scratch ----------------------------------------------------
__device__ float g_u[NND * 128];               // masked PReLU(x)
__device__ float g_U1[NND * 128];              // u + sum of u[src] over in-edges
__device__ float g_S[NND * 9];                 // sum of edge_attr over in-edges
__device__ float g_z[NND * 256];               // pre-BN hidden
__device__ float g_P[9 * 256];                 // W_e @ W1_bot
__device__ float g_q1[256];                    // b_e @ W1_bot
__device__ float g_cs[256];                    // column sums of z
__device__ float g_cq[256];                    // column sums of z^2
__device__ float g_a[256];                     // BN scale
__device__ float g_bb[256];                    // BN shift
__device__ __align__(16) __half g_Bz[256 * SAPAD];       // Wfold^T fp16 plane
__device__ __align__(16) __half g_Bo[2 * 128 * SAPAD];   // W2^T [kc] fp16 planes
// CSR scratch
__device__ int g_cnt[NND];
__device__ int g_offp[NND];
__device__ int g_bs[NSCB];
__device__ int g_bo[NSCB + 1];
__device__ int g_off[NND + 1];
__device__ int g_cur[NND];
__device__ int2 g_se[EDG];                     // (src, edge_id)

// ---------------- helpers -----------------------------------------------------
__device__ __forceinline__ uint32_t smem_u32(const void* p) {
    uint32_t a;
    asm("{ .reg .u64 t; cvta.to.shared.u64 t, %1; cvt.u32.u64 %0, t; }" : "=r"(a) : "l"(p));
    return a;
}
__device__ __forceinline__ void ldsm4(uint32_t& r0, uint32_t& r1, uint32_t& r2, uint32_t& r3,
                                      uint32_t addr) {
    asm volatile("ldmatrix.sync.aligned.m8n8.x4.shared.b16 {%0,%1,%2,%3}, [%4];"
                 : "=r"(r0), "=r"(r1), "=r"(r2), "=r"(r3) : "r"(addr));
}
__device__ __forceinline__ void mma_f16(float* c, const uint32_t* a, uint32_t b0, uint32_t b1) {
    asm volatile(
        "mma.sync.aligned.m16n8k16.row.col.f32.f16.f16.f32 "
        "{%0,%1,%2,%3}, {%4,%5,%6,%7}, {%8,%9}, {%0,%1,%2,%3};"
        : "+f"(c[0]), "+f"(c[1]), "+f"(c[2]), "+f"(c[3])
        : "r"(a[0]), "r"(a[1]), "r"(a[2]), "r"(a[3]), "r"(b0), "r"(b1));
}
__device__ __forceinline__ uint32_t pack_f16(float a, float b) {
    __half2 h = make_half2(__float2half_rn(a), __float2half_rn(b));
    return *(uint32_t*)&h;
}
// fp32x4 -> fp16 hi/lo split, store at element index idx (mult of 4)
__device__ __forceinline__ void split_store_h(__half* hi, __half* lo, int idx, float4 g) {
    __half hx = __float2half_rn(g.x), hy = __float2half_rn(g.y);
    __half hz = __float2half_rn(g.z), hw = __float2half_rn(g.w);
    __half lx = __float2half_rn(g.x - __half2float(hx));
    __half ly = __float2half_rn(g.y - __half2float(hy));
    __half lz = __float2half_rn(g.z - __half2float(hz));
    __half lw = __float2half_rn(g.w - __half2float(hw));
    __half2 h0 = make_half2(hx, hy), h1 = make_half2(hz, hw);
    __half2 l0 = make_half2(lx, ly), l1 = make_half2(lz, lw);
    uint2 h, l;
    h.x = *(uint32_t*)&h0; h.y = *(uint32_t*)&h1;
    l.x = *(uint32_t*)&l0; l.y = *(uint32_t*)&l1;
    *(uint2*)&hi[idx] = h;
    *(uint2*)&lo[idx] = l;
}

// ---------------- kernel 1: u = PReLU(x) -------------------------------------
__global__ void __launch_bounds__(256) prep_kernel(const float* __restrict__ x,
                                                   const float* __restrict__ pa) {
    const float a = *pa;
    size_t i = (size_t)blockIdx.x * 256 + threadIdx.x;
    if (i >= (size_t)NND * 32) return;
    float4 g = *(const float4*)&x[i * 4];
    g.x = g.x >= 0.f ? g.x : a * g.x;
    g.y = g.y >= 0.f ? g.y : a * g.y;
    g.z = g.z >= 0.f ? g.z : a * g.z;
    g.w = g.w >= 0.f ? g.w : a * g.w;
    *(float4*)&g_u[i * 4] = g;
}

// ---------------- kernel 2: zero masked rows ---------------------------------
__global__ void mask_kernel(const int* __restrict__ idx, int n) {
    int i = blockIdx.x;
    if (i >= n) return;
    unsigned v = (unsigned)idx[i];
    if (v < NND)
        *(float4*)&g_u[(size_t)v * 128 + threadIdx.x * 4] =
            make_float4(0.f, 0.f, 0.f, 0.f);
}

// ---------------- CSR build ---------------------------------------------------
__global__ void __launch_bounds__(256) hist_kernel(const int* __restrict__ ei) {
    int e = blockIdx.x * 256 + threadIdx.x;
    if (e >= EDG) return;
    unsigned s = (unsigned)ei[e];
    unsigned d = (unsigned)ei[EDG + e];
    if (s >= NND || d >= NND) return;
    atomicAdd(&g_cnt[d], 1);
}

__global__ void __launch_bounds__(256) scan1_kernel() {
    __shared__ int s[256];
    int t = threadIdx.x;
    int idx = blockIdx.x * 256 + t;
    int v = (idx < NND) ? g_cnt[idx] : 0;
    int val = v;
    s[t] = val;
    __syncthreads();
#pragma unroll
    for (int off = 1; off < 256; off <<= 1) {
        int add = (t >= off) ? s[t - off] : 0;
        __syncthreads();
        val += add;
        s[t] = val;
        __syncthreads();
    }
    if (idx < NND) g_offp[idx] = val - v;
    if (t == 255) g_bs[blockIdx.x] = val;
}

__global__ void __launch_bounds__(256) scan2_kernel() {
    __shared__ int s[256];
    int t = threadIdx.x;
    int v = (t < NSCB) ? g_bs[t] : 0;
    int val = v;
    s[t] = val;
    __syncthreads();
#pragma unroll
    for (int off = 1; off < 256; off <<= 1) {
        int add = (t >= off) ? s[t - off] : 0;
        __syncthreads();
        val += add;
        s[t] = val;
        __syncthreads();
    }
    if (t < NSCB) g_bo[t] = val - v;
    if (t == 255) g_bo[NSCB] = val;
}

__global__ void __launch_bounds__(256) scan3_kernel() {
    int idx = blockIdx.x * 256 + threadIdx.x;
    if (idx < NND) {
        int o = g_offp[idx] + g_bo[blockIdx.x];
        g_off[idx] = o;
        g_cur[idx] = o;
    }
    if (idx == 0) g_off[NND] = g_bo[NSCB];
}

__global__ void __launch_bounds__(256) fill_kernel(const int* __restrict__ ei) {
    int e = blockIdx.x * 256 + threadIdx.x;
    if (e >= EDG) return;
    unsigned s = (unsigned)ei[e];
    unsigned d = (unsigned)ei[EDG + e];
    if (s >= NND || d >= NND) return;
    int p = atomicAdd(&g_cur[d], 1);
    g_se[p] = make_int2((int)s, e);
}

// ---------------- aggregate: U1[v] = u[v] + sum u[src]; S[v] = sum ea --------
__global__ void __launch_bounds__(256) aggregate_kernel(const float* __restrict__ ea) {
    int w = (int)((blockIdx.x * 256u + threadIdx.x) >> 5);
    int lane = threadIdx.x & 31;
    if (w >= NND) return;
    int nb = g_off[w], ne = g_off[w + 1];
    float4 acc = *(const float4*)&g_u[(size_t)w * 128 + lane * 4];
    float sa = 0.f;
    int i = nb;
    for (; i + 4 <= ne; i += 4) {
        int2 p0 = g_se[i], p1 = g_se[i + 1], p2 = g_se[i + 2], p3 = g_se[i + 3];
        float4 a = *(const float4*)&g_u[(size_t)p0.x * 128 + lane * 4];
        float4 b = *(const float4*)&g_u[(size_t)p1.x * 128 + lane * 4];
        float4 c = *(const float4*)&g_u[(size_t)p2.x * 128 + lane * 4];
        float4 d = *(const float4*)&g_u[(size_t)p3.x * 128 + lane * 4];
        acc.x += a.x + b.x + c.x + d.x;
        acc.y += a.y + b.y + c.y + d.y;
        acc.z += a.z + b.z + c.z + d.z;
        acc.w += a.w + b.w + c.w + d.w;
        if (lane < 9) {
            sa += ea[(size_t)p0.y * 9 + lane] + ea[(size_t)p1.y * 9 + lane]
                + ea[(size_t)p2.y * 9 + lane] + ea[(size_t)p3.y * 9 + lane];
        }
    }
    for (; i < ne; i++) {
        int2 p0 = g_se[i];
        float4 a = *(const float4*)&g_u[(size_t)p0.x * 128 + lane * 4];
        acc.x += a.x; acc.y += a.y; acc.z += a.z; acc.w += a.w;
        if (lane < 9) sa += ea[(size_t)p0.y * 9 + lane];
    }
    *(float4*)&g_U1[(size_t)w * 128 + lane * 4] = acc;
    if (lane < 9) g_S[(size_t)w * 9 + lane] = sa;
}

// ---------------- merged weight prep: 0-7 fold_bz, 8-15 fold_bo, 16-25 precomp
__global__ void __launch_bounds__(256) weights_kernel(const float* __restrict__ Wenc,
                                                      const float* __restrict__ W1,
                                                      const float* __restrict__ W2,
                                                      const float* __restrict__ We,
                                                      const float* __restrict__ be) {
    __shared__ float ws[32 * 128];
    const int b = blockIdx.x;
    if (b < 8) {
        const int k0 = b * 16, c = threadIdx.x;
        for (int i = threadIdx.x; i < 512; i += 256)
            ((float4*)ws)[i] = ((const float4*)(Wenc + k0 * 128))[i];
        __syncthreads();
        float acc[16];
#pragma unroll
        for (int r = 0; r < 16; r++) acc[r] = 0.f;
        for (int m = 0; m < 128; m++) {
            float w1 = W1[m * 256 + c];
#pragma unroll
            for (int r = 0; r < 16; r++) acc[r] += ws[r * 128 + m] * w1;
        }
        uint32_t h[8];
#pragma unroll
        for (int r = 0; r < 8; r++) h[r] = pack_f16(acc[2 * r], acc[2 * r + 1]);
        uint4* ph = (uint4*)&g_Bz[c * SAPAD + k0];
        ph[0] = make_uint4(h[0], h[1], h[2], h[3]);
        ph[1] = make_uint4(h[4], h[5], h[6], h[7]);
    } else if (b < 16) {
        const int k0 = (b - 8) * 32;
        const int kc = k0 >> 7, kk0 = k0 & 127;
        for (int i = threadIdx.x; i < 1024; i += 256)
            ((float4*)ws)[i] = ((const float4*)(W2 + k0 * 128))[i];
        __syncthreads();
        const int n = threadIdx.x >> 1, kl0 = (threadIdx.x & 1) * 16;
        uint32_t h[8];
#pragma unroll
        for (int q = 0; q < 8; q++)
            h[q] = pack_f16(ws[(kl0 + 2 * q) * 128 + n], ws[(kl0 + 2 * q + 1) * 128 + n]);
        uint4* ph = (uint4*)&g_Bo[kc * 128 * SAPAD + n * SAPAD + kk0 + kl0];
        ph[0] = make_uint4(h[0], h[1], h[2], h[3]);
        ph[1] = make_uint4(h[4], h[5], h[6], h[7]);
    } else {
        const int j = b - 16, c = threadIdx.x;
        if (c < 128) ws[c] = (j < 9) ? We[j * 128 + c] : be[c];
        __syncthreads();
        float acc = 0.f;
#pragma unroll 8
        for (int m = 0; m < 128; m++) acc += ws[m] * W1[(128 + m) * 256 + c];
        if (j < 9) g_P[j * 256 + c] = acc;
        else       g_q1[c] = acc;
    }
}

// ---------------- kernel 5: HMMA gemm_z (fp16 2-term) ------------------------
#define ZA_HI 0
#define ZA_LO 34816
#define ZB    69632
#define ZP    139264
#define ZQ1   148480
#define ZPC   149504
#define ZSS   150528
#define ZCS   156672
#define ZCQ   157696
#define ZSMEM 158720

__global__ void __launch_bounds__(256, 1) gemm_z_tc(const float* __restrict__ b1) {
    extern __shared__ __align__(16) unsigned char sm[];
    const uint32_t sbase = smem_u32(sm);
    const int tid = threadIdx.x, w = tid >> 5, lid = tid & 31;
    const int rowBase = blockIdx.x * 128;
    float* Psm = (float*)(sm + ZP);
    float* Q1s = (float*)(sm + ZQ1);
    float* PCs = (float*)(sm + ZPC);
    float* Ssm = (float*)(sm + ZSS);
    float* CSs = (float*)(sm + ZCS);
    float* CQs = (float*)(sm + ZCQ);

    for (int i = tid; i < 2304; i += 256) Psm[i] = g_P[i];
    Q1s[tid] = g_q1[tid];
    PCs[tid] = g_P[7 * 256 + tid] + b1[tid];
    CSs[tid] = 0.f;
    CQs[tid] = 0.f;
    for (int i = tid; i < 1280; i += 256) {
        int r = i / 10, j = i % 10;
        int grow = rowBase + r;
        float v = 0.f;
        if (grow < NND)
            v = (j < 9) ? g_S[(size_t)grow * 9 + j]
                        : (float)(g_off[grow + 1] - g_off[grow]);
        Ssm[r * 12 + j] = v;
    }
    // stage A hi/lo (fp16)
    {
        int r = tid >> 1, ch = (tid & 1) * 64;
        int grow = rowBase + r;
        __half* ah = (__half*)(sm + ZA_HI);
        __half* al = (__half*)(sm + ZA_LO);
        if (grow < NND) {
            const float* src = &g_U1[(size_t)grow * 128 + ch];
#pragma unroll
            for (int j = 0; j < 16; j++)
                split_store_h(ah, al, r * SAPAD + ch + j * 4, *(const float4*)&src[j * 4]);
        } else {
            float4 zz = make_float4(0.f, 0.f, 0.f, 0.f);
#pragma unroll
            for (int j = 0; j < 16; j++) split_store_h(ah, al, r * SAPAD + ch + j * 4, zz);
        }
    }
    for (int i = tid * 16; i < 69632; i += 256 * 16)
        *(float4*)(sm + ZB + i) = *(const float4*)((const unsigned char*)g_Bz + i);
    __syncthreads();

    float acc[8][4][4];
#pragma unroll
    for (int m = 0; m < 8; m++)
#pragma unroll
        for (int n = 0; n < 4; n++)
#pragma unroll
            for (int e = 0; e < 4; e++) acc[m][n][e] = 0.f;

    const uint32_t a_lane = (uint32_t)((((lid & 7) + 8 * ((lid >> 3) & 1)) * SAPAD + 8 * (lid >> 4)) * 2);
    const uint32_t b_lane = (uint32_t)((((lid & 7) + 8 * (lid >> 4)) * SAPAD + 8 * ((lid >> 3) & 1)) * 2);
    const uint32_t bb = sbase + ZB + b_lane + (uint32_t)(w * 32 * SAPAD) * 2;

#pragma unroll
    for (int t = 0; t < 2; t++) {
        uint32_t abase = sbase + (t == 1 ? ZA_LO : ZA_HI) + a_lane;
#pragma unroll
        for (int kt = 0; kt < 8; kt++) {
            uint32_t k2 = kt * 32;
            uint32_t af[8][4];
#pragma unroll
            for (int mt = 0; mt < 8; mt++)
                ldsm4(af[mt][0], af[mt][1], af[mt][2], af[mt][3],
                      abase + mt * (16 * SAPAD * 2) + k2);
            uint32_t bf0[4], bf1[4];
            ldsm4(bf0[0], bf0[1], bf0[2], bf0[3], bb + k2);
            ldsm4(bf1[0], bf1[1], bf1[2], bf1[3], bb + 16 * SAPAD * 2 + k2);
#pragma unroll
            for (int mt = 0; mt < 8; mt++) {
                mma_f16(acc[mt][0], af[mt], bf0[0], bf0[1]);
                mma_f16(acc[mt][1], af[mt], bf0[2], bf0[3]);
                mma_f16(acc[mt][2], af[mt], bf1[0], bf1[1]);
                mma_f16(acc[mt][3], af[mt], bf1[2], bf1[3]);
            }
        }
    }

    // epilogue
    const int gid = lid >> 2, tig = lid & 3;
    float colS[8], colQ[8];
#pragma unroll
    for (int e = 0; e < 8; e++) { colS[e] = 0.f; colQ[e] = 0.f; }
#pragma unroll
    for (int mt = 0; mt < 8; mt++) {
        int r0 = mt * 16 + gid, r1 = r0 + 8;
        int gr0 = rowBase + r0, gr1 = rowBase + r1;
        bool v0 = gr0 < NND, v1 = gr1 < NND;
        float s0[10], s1[10];
#pragma unroll
        for (int j = 0; j < 10; j++) { s0[j] = Ssm[r0 * 12 + j]; s1[j] = Ssm[r1 * 12 + j]; }
        float d0 = s0[9] + 1.f, d1v = s1[9] + 1.f;
#pragma unroll
        for (int nt = 0; nt < 4; nt++) {
            int c0 = w * 32 + nt * 8 + 2 * tig, c1 = c0 + 1;
            float v00 = acc[mt][nt][0] + d0 * Q1s[c0] + PCs[c0];
            float v01 = acc[mt][nt][1] + d0 * Q1s[c1] + PCs[c1];
            float v10 = acc[mt][nt][2] + d1v * Q1s[c0] + PCs[c0];
            float v11 = acc[mt][nt][3] + d1v * Q1s[c1] + PCs[c1];
#pragma unroll
            for (int j = 0; j < 9; j++) {
                float p0 = Psm[j * 256 + c0], p1 = Psm[j * 256 + c1];
                v00 += s0[j] * p0; v01 += s0[j] * p1;
                v10 += s1[j] * p0; v11 += s1[j] * p1;
            }
            if (v0) {
                *(float2*)&g_z[(size_t)gr0 * 256 + c0] = make_float2(v00, v01);
                colS[nt * 2] += v00; colQ[nt * 2] += v00 * v00;
                colS[nt * 2 + 1] += v01; colQ[nt * 2 + 1] += v01 * v01;
            }
            if (v1) {
                *(float2*)&g_z[(size_t)gr1 * 256 + c0] = make_float2(v10, v11);
                colS[nt * 2] += v10; colQ[nt * 2] += v10 * v10;
                colS[nt * 2 + 1] += v11; colQ[nt * 2 + 1] += v11 * v11;
            }
        }
    }
#pragma unroll
    for (int nt = 0; nt < 4; nt++) {
#pragma unroll
        for (int e = 0; e < 2; e++) {
            int c = w * 32 + nt * 8 + 2 * tig + e;
            atomicAdd(&CSs[c], colS[nt * 2 + e]);
            atomicAdd(&CQs[c], colQ[nt * 2 + e]);
        }
    }
    __syncthreads();
    atomicAdd(&g_cs[tid], CSs[tid]);
    atomicAdd(&g_cq[tid], CQs[tid]);
}

// ---------------- kernel 6: BN finalize --------------------------------------
__global__ void bn_kernel(const float* __restrict__ gamma,
                          const float* __restrict__ beta) {
    int c = threadIdx.x;
    const float invN = 1.f / (float)NND;
    float m = g_cs[c] * invN;
    float var = g_cq[c] * invN - m * m;
    float av = gamma[c] * rsqrtf(var + 1e-5f);
    g_a[c] = av;
    g_bb[c] = beta[c] - m * av;
}

// ---------------- kernel 7: HMMA gemm_o (fp16 2-term) ------------------------
#define OA_HI 0
#define OA_LO 34816
#define OB    69632
#define OSA   139264
#define OSB   140288
#define OB2   141312
#define OSMEM 141824

__global__ void __launch_bounds__(256, 1) gemm_o_tc(const float* __restrict__ b2,
                                                    float* __restrict__ out) {
    extern __shared__ __align__(16) unsigned char sm[];
    const uint32_t sbase = smem_u32(sm);
    const int tid = threadIdx.x, w = tid >> 5, lid = tid & 31;
    const int rowBase = blockIdx.x * 128;
    float* SAs = (float*)(sm + OSA);
    float* SBs = (float*)(sm + OSB);
    float* B2s = (float*)(sm + OB2);
    SAs[tid] = g_a[tid];
    SBs[tid] = g_bb[tid];
    if (tid < 128) B2s[tid] = b2[tid];
    for (int i = tid * 16; i < 69632; i += 256 * 16)
        *(float4*)(sm + OB + i) = *(const float4*)((const unsigned char*)g_Bo + i);

    float acc[4][4][4];
#pragma unroll
    for (int m = 0; m < 4; m++)
#pragma unroll
        for (int n = 0; n < 4; n++)
#pragma unroll
            for (int e = 0; e < 4; e++) acc[m][n][e] = 0.f;

    const uint32_t a_lane = (uint32_t)((((lid & 7) + 8 * ((lid >> 3) & 1)) * SAPAD + 8 * (lid >> 4)) * 2);
    const uint32_t b_lane = (uint32_t)((((lid & 7) + 8 * (lid >> 4)) * SAPAD + 8 * ((lid >> 3) & 1)) * 2);
    const uint32_t a_mbase = (uint32_t)((w >> 2) * 64 * SAPAD * 2);
    const uint32_t b_nbase = (uint32_t)((w & 3) * 32 * SAPAD * 2);

    for (int kc = 0; kc < 2; kc++) {
        __syncthreads();
        {
            int r = tid >> 1, ch = (tid & 1) * 64;
            int grow = rowBase + r;
            __half* ah = (__half*)(sm + OA_HI);
            __half* al = (__half*)(sm + OA_LO);
            if (grow < NND) {
                const float* src = &g_z[(size_t)grow * 256 + kc * 128 + ch];
#pragma unroll
                for (int j = 0; j < 16; j++) {
                    float4 g = *(const float4*)&src[j * 4];
                    int c0 = kc * 128 + ch + j * 4;
                    g.x = fmaxf(g.x * SAs[c0 + 0] + SBs[c0 + 0], 0.f);
                    g.y = fmaxf(g.y * SAs[c0 + 1] + SBs[c0 + 1], 0.f);
                    g.z = fmaxf(g.z * SAs[c0 + 2] + SBs[c0 + 2], 0.f);
                    g.w = fmaxf(g.w * SAs[c0 + 3] + SBs[c0 + 3], 0.f);
                    split_store_h(ah, al, r * SAPAD + ch + j * 4, g);
                }
            } else {
                float4 zz = make_float4(0.f, 0.f, 0.f, 0.f);
#pragma unroll
                for (int j = 0; j < 16; j++) split_store_h(ah, al, r * SAPAD + ch + j * 4, zz);
            }
        }
        __syncthreads();
        const uint32_t bb = sbase + OB + (uint32_t)(kc * 34816) + b_lane + b_nbase;
#pragma unroll
        for (int t = 0; t < 2; t++) {
            uint32_t abase = sbase + (t == 1 ? OA_LO : OA_HI) + a_lane + a_mbase;
#pragma unroll
            for (int kt = 0; kt < 8; kt++) {
                uint32_t k2 = kt * 32;
                uint32_t af[4][4];
#pragma unroll
                for (int mt = 0; mt < 4; mt++)
                    ldsm4(af[mt][0], af[mt][1], af[mt][2], af[mt][3],
                          abase + mt * (16 * SAPAD * 2) + k2);
                uint32_t bf0[4], bf1[4];
                ldsm4(bf0[0], bf0[1], bf0[2], bf0[3], bb + k2);
                ldsm4(bf1[0], bf1[1], bf1[2], bf1[3], bb + 16 * SAPAD * 2 + k2);
#pragma unroll
                for (int mt = 0; mt < 4; mt++) {
                    mma_f16(acc[mt][0], af[mt], bf0[0], bf0[1]);
                    mma_f16(acc[mt][1], af[mt], bf0[2], bf0[3]);
                    mma_f16(acc[mt][2], af[mt], bf1[0], bf1[1]);
                    mma_f16(acc[mt][3], af[mt], bf1[2], bf1[3]);
                }
            }
        }
    }

    const int gid = lid >> 2, tig = lid & 3;
#pragma unroll
    for (int mt = 0; mt < 4; mt++) {
        int r0 = (w >> 2) * 64 + mt * 16 + gid, r1 = r0 + 8;
        int gr0 = rowBase + r0, gr1 = rowBase + r1;
#pragma unroll
        for (int nt = 0; nt < 4; nt++) {
            int c0 = (w & 3) * 32 + nt * 8 + 2 * tig;
            if (gr0 < NND)
                *(float2*)&out[(size_t)gr0 * 128 + c0] =
                    make_float2(acc[mt][nt][0] + B2s[c0], acc[mt][nt][1] + B2s[c0 + 1]);
            if (gr1 < NND)
                *(float2*)&out[(size_t)gr1 * 128 + c0] =
                    make_float2(acc[mt][nt][2] + B2s[c0], acc[mt][nt][3] + B2s[c0 + 1]);
        }
    }
}

// ---------------- launch ----------------------------------------------------
extern "C" void kernel_launch(void* const* d_in, const int* in_sizes, int n_in,
                              void* d_out, int out_size) {
    const float* x     = (const float*)d_in[0];
    const int*   ei    = (const int*)d_in[1];
    const float* ea    = (const float*)d_in[2];
    const int*   mask  = (const int*)d_in[3];
    const float* pa    = (const float*)d_in[4];
    const float* Wenc  = (const float*)d_in[5];
    const float* We    = (const float*)d_in[6];
    const float* be    = (const float*)d_in[7];
    const float* W1    = (const float*)d_in[8];
    const float* b1    = (const float*)d_in[9];
    const float* gamma = (const float*)d_in[10];
    const float* beta  = (const float*)d_in[11];
    const float* W2    = (const float*)d_in[12];
    const float* b2    = (const float*)d_in[13];
    float*       out   = (float*)d_out;
    const int nmask = in_sizes[3];

    cudaFuncSetAttribute(gemm_z_tc, cudaFuncAttributeMaxDynamicSharedMemorySize, ZSMEM);
    cudaFuncSetAttribute(gemm_o_tc, cudaFuncAttributeMaxDynamicSharedMemorySize, OSMEM);

    void *pcnt, *pcs, *pcq;
    cudaGetSymbolAddress(&pcnt, g_cnt);
    cudaGetSymbolAddress(&pcs, g_cs);
    cudaGetSymbolAddress(&pcq, g_cq);
    cudaMemsetAsync(pcnt, 0, sizeof(int) * NND, 0);
    cudaMemsetAsync(pcs, 0, sizeof(float) * 256, 0);
    cudaMemsetAsync(pcq, 0, sizeof(float) * 256, 0);

    prep_kernel<<<(NND * 32 + 255) / 256, 256>>>(x, pa);
    if (nmask > 0) mask_kernel<<<nmask, 32>>>(mask, nmask);
    hist_kernel<<<(EDG + 255) / 256, 256>>>(ei);
    scan1_kernel<<<NSCB, 256>>>();
    scan2_kernel<<<1, 256>>>();
    scan3_kernel<<<NSCB, 256>>>();
    fill_kernel<<<(EDG + 255) / 256, 256>>>(ei);
    aggregate_kernel<<<(NND * 32 + 255) / 256, 256>>>(ea);
    weights_kernel<<<26, 256>>>(Wenc, W1, W2, We, be);
    gemm_z_tc<<<NTILES, 256, ZSMEM>>>(b1);
    bn_kernel<<<1, 256>>>(gamma, beta);
    gemm_o_tc<<<NTILES, 256, OSMEM>>>(b2, out);
}